// round 10
// baseline (speedup 1.0000x reference)
#include <cuda_runtime.h>
#include <cuda_fp16.h>

// Problem constants
#define FX 80
#define NX 128
#define HH 512
#define WW 1024
#define BC 16                 // B*C fused channel count
#define M  (FX * NX * NX)     // 1310720 texels per channel
#define HW (HH * WW)          // 524288 pixels

// Scratch: x transposed + converted to fp16, layout [M][16] halfs (32B/texel).
// 40MB -> target: keep L2-resident (126MB L2) through the sample pass.
__device__ __align__(128) __half g_xt[(size_t)M * BC];

__device__ __forceinline__ unsigned int h2u(__half2 h) {
    return *reinterpret_cast<unsigned int*>(&h);
}

// ---------------------------------------------------------------------------
// Pass 1: fused transpose+convert, register-only, 2 texels per thread.
// Warp does 16 coalesced LDG.64 (one per channel, 256B per warp per instr);
// lane t then holds both texels' 16 channels in registers -> convert and
// write 2 x 32B via 4 STG.128. Halves load-instruction count vs scalar at
// ~48 live regs (occupancy still ample for streaming MLP=16).
// ---------------------------------------------------------------------------
__global__ void __launch_bounds__(256) transpose_kernel(const float* __restrict__ x) {
    const int m0 = (blockIdx.x * 256 + threadIdx.x) * 2;   // first of 2 texels

    float2 v[16];
#pragma unroll
    for (int c = 0; c < 16; c++)
        v[c] = *reinterpret_cast<const float2*>(x + (size_t)c * M + m0);  // 16 x LDG.64

    uint4* dst = reinterpret_cast<uint4*>(g_xt + (size_t)m0 * BC);

    // texel 0 (x components)
    {
        unsigned int w[8];
#pragma unroll
        for (int j = 0; j < 8; j++)
            w[j] = h2u(__floats2half2_rn(v[2 * j].x, v[2 * j + 1].x));
        dst[0] = make_uint4(w[0], w[1], w[2], w[3]);
        dst[1] = make_uint4(w[4], w[5], w[6], w[7]);
    }
    // texel 1 (y components)
    {
        unsigned int w[8];
#pragma unroll
        for (int j = 0; j < 8; j++)
            w[j] = h2u(__floats2half2_rn(v[2 * j].y, v[2 * j + 1].y));
        dst[2] = make_uint4(w[0], w[1], w[2], w[3]);
        dst[3] = make_uint4(w[4], w[5], w[6], w[7]);
    }
}

// accumulate 8 fp16 channels (one uint4) into fp32 accumulators with weight w
__device__ __forceinline__ void acc8(float* r, const uint4& a, float w) {
    const __half2* h = reinterpret_cast<const __half2*>(&a);
#pragma unroll
    for (int j = 0; j < 4; j++) {
        float2 f = __half22float2(h[j]);
        r[2 * j]     = fmaf(f.x, w, r[2 * j]);
        r[2 * j + 1] = fmaf(f.y, w, r[2 * j + 1]);
    }
}

// ---------------------------------------------------------------------------
// Pass 2: bilinear gather (R4 recipe, measured best = 17.6-17.9us) with L2
// residency control: uv/quad via __ldcs (read-once streaming), out via __stcs
// (evict-first) so the 40MB table keeps its L2 footprint and gathers hit L2.
// Block = 256 threads = 128 pixels x 2 half-groups; 4 independent LDG.128
// per thread; direct 64B-coalesced stores per plane. No smem, no barriers.
// ---------------------------------------------------------------------------
__global__ void __launch_bounds__(256) sample_kernel(const int*   __restrict__ quad,
                                                     const float* __restrict__ uv,
                                                     float*       __restrict__ out) {
    const int t   = threadIdx.x;
    const int p   = t >> 1;            // pixel-in-tile 0..127
    const int hg  = t & 1;             // half-group: channels hg*8 .. hg*8+7
    const int pix = blockIdx.x * 128 + p;

    const float2 uvp = __ldcs(reinterpret_cast<const float2*>(uv) + pix);
    const int    f   = __ldcs(quad + pix);

    int u0 = min(max((int)floorf(uvp.x), 0), NX - 2);
    int v0 = min(max((int)floorf(uvp.y), 0), NX - 2);
    const float du = uvp.x - (float)u0;
    const float dv = uvp.y - (float)v0;

    const __half* base = g_xt + ((size_t)((f * NX + v0) * NX + u0)) * BC + hg * 8;
    const uint4 a00 = *reinterpret_cast<const uint4*>(base);
    const uint4 a01 = *reinterpret_cast<const uint4*>(base + BC);
    const uint4 a10 = *reinterpret_cast<const uint4*>(base + BC * NX);
    const uint4 a11 = *reinterpret_cast<const uint4*>(base + BC * NX + BC);

    const float w00 = (1.0f - du) * (1.0f - dv);
    const float w01 = du * (1.0f - dv);
    const float w10 = (1.0f - du) * dv;
    const float w11 = du * dv;

    float r[8];
#pragma unroll
    for (int j = 0; j < 8; j++) r[j] = 0.0f;
    acc8(r, a00, w00);
    acc8(r, a01, w01);
    acc8(r, a10, w10);
    acc8(r, a11, w11);

    // direct coalesced stores, evict-first so they don't displace the table
    float* o = out + (size_t)(hg * 8) * HW + pix;
#pragma unroll
    for (int k = 0; k < 8; k++)
        __stcs(o + (size_t)k * HW, r[k]);
}

extern "C" void kernel_launch(void* const* d_in, const int* in_sizes, int n_in,
                              void* d_out, int out_size) {
    const float* x    = (const float*)d_in[0];   // [2,8,80,128,128] fp32
    const int*   quad = (const int*)  d_in[1];   // [512,1024] int32
    const float* uv   = (const float*)d_in[2];   // [512,1024,2] fp32
    float*       out  = (float*)d_out;           // [2,8,512,1024] fp32

    transpose_kernel<<<M / 512, 256>>>(x);            // 2560 blocks
    sample_kernel<<<HW / 128, 256>>>(quad, uv, out);  // 4096 blocks
}

// round 11
// speedup vs baseline: 1.0816x; 1.0816x over previous
#include <cuda_runtime.h>
#include <cuda_fp16.h>

// Problem constants
#define FX 80
#define NX 128
#define HH 512
#define WW 1024
#define BC 16                 // B*C fused channel count
#define M  (FX * NX * NX)     // 1310720 texels per channel
#define HW (HH * WW)          // 524288 pixels

// Scratch: x transposed + converted to fp16, layout [M][16] halfs (32B/texel).
// 40MB -> goal: keep DIRTY-RESIDENT in L2 (126MB) until the sample pass reads
// it, deferring its DRAM write-back out of the transpose's critical path.
__device__ __align__(128) __half g_xt[(size_t)M * BC];

__device__ __forceinline__ unsigned int h2u(__half2 h) {
    return *reinterpret_cast<unsigned int*>(&h);
}

// ---------------------------------------------------------------------------
// Pass 1: fused transpose+convert, register-only scalar (the measured-best
// R3/R9 shape), with one change: input reads use __ldcs (evict-first).
// The 80MB of x is dead after one use; without the hint it floods L2 and
// evicts the freshly-written dirty table lines, forcing their 40MB
// write-back INSIDE this kernel's timed window. With .cs reads the table
// stays L2-resident and transpose DRAM traffic drops to ~80MB.
// ---------------------------------------------------------------------------
__global__ void __launch_bounds__(256) transpose_kernel(const float* __restrict__ x) {
    const int m = blockIdx.x * 256 + threadIdx.x;   // one texel per thread

    float v[16];
#pragma unroll
    for (int c = 0; c < 16; c++)
        v[c] = __ldcs(x + (size_t)c * M + m);       // 16 coalesced streaming LDG.32

    unsigned int w[8];
#pragma unroll
    for (int j = 0; j < 8; j++)
        w[j] = h2u(__floats2half2_rn(v[2 * j], v[2 * j + 1]));

    uint4* dst = reinterpret_cast<uint4*>(g_xt + (size_t)m * BC);
    dst[0] = make_uint4(w[0], w[1], w[2], w[3]);
    dst[1] = make_uint4(w[4], w[5], w[6], w[7]);
}

// accumulate 8 fp16 channels (one uint4) into fp32 accumulators with weight w
__device__ __forceinline__ void acc8(float* r, const uint4& a, float w) {
    const __half2* h = reinterpret_cast<const __half2*>(&a);
#pragma unroll
    for (int j = 0; j < 4; j++) {
        float2 f = __half22float2(h[j]);
        r[2 * j]     = fmaf(f.x, w, r[2 * j]);
        r[2 * j + 1] = fmaf(f.y, w, r[2 * j + 1]);
    }
}

// ---------------------------------------------------------------------------
// Pass 2: bilinear gather — R9 exact (measured best 17.6-17.9us; the R10
// cache hints were neutral, dropped). Block = 256 threads = 128 pixels x 2
// half-groups; 4 independent LDG.128 per thread (16B = 8 fp16 channels per
// corner); direct 64B-coalesced stores per plane. No smem, no barriers.
// ---------------------------------------------------------------------------
__global__ void __launch_bounds__(256) sample_kernel(const int*   __restrict__ quad,
                                                     const float* __restrict__ uv,
                                                     float*       __restrict__ out) {
    const int t   = threadIdx.x;
    const int p   = t >> 1;            // pixel-in-tile 0..127
    const int hg  = t & 1;             // half-group: channels hg*8 .. hg*8+7
    const int pix = blockIdx.x * 128 + p;

    const float2 uvp = reinterpret_cast<const float2*>(uv)[pix];
    const int    f   = quad[pix];

    int u0 = min(max((int)floorf(uvp.x), 0), NX - 2);
    int v0 = min(max((int)floorf(uvp.y), 0), NX - 2);
    const float du = uvp.x - (float)u0;
    const float dv = uvp.y - (float)v0;

    const __half* base = g_xt + ((size_t)((f * NX + v0) * NX + u0)) * BC + hg * 8;
    const uint4 a00 = *reinterpret_cast<const uint4*>(base);
    const uint4 a01 = *reinterpret_cast<const uint4*>(base + BC);
    const uint4 a10 = *reinterpret_cast<const uint4*>(base + BC * NX);
    const uint4 a11 = *reinterpret_cast<const uint4*>(base + BC * NX + BC);

    const float w00 = (1.0f - du) * (1.0f - dv);
    const float w01 = du * (1.0f - dv);
    const float w10 = (1.0f - du) * dv;
    const float w11 = du * dv;

    float r[8];
#pragma unroll
    for (int j = 0; j < 8; j++) r[j] = 0.0f;
    acc8(r, a00, w00);
    acc8(r, a01, w01);
    acc8(r, a10, w10);
    acc8(r, a11, w11);

    // direct coalesced stores: 16 lanes of same hg -> 16 consecutive pixels
    float* o = out + (size_t)(hg * 8) * HW + pix;
#pragma unroll
    for (int k = 0; k < 8; k++)
        o[(size_t)k * HW] = r[k];
}

extern "C" void kernel_launch(void* const* d_in, const int* in_sizes, int n_in,
                              void* d_out, int out_size) {
    const float* x    = (const float*)d_in[0];   // [2,8,80,128,128] fp32
    const int*   quad = (const int*)  d_in[1];   // [512,1024] int32
    const float* uv   = (const float*)d_in[2];   // [512,1024,2] fp32
    float*       out  = (float*)d_out;           // [2,8,512,1024] fp32

    transpose_kernel<<<M / 256, 256>>>(x);            // 5120 blocks
    sample_kernel<<<HW / 128, 256>>>(quad, uv, out);  // 4096 blocks
}